// round 4
// baseline (speedup 1.0000x reference)
#include <cuda_runtime.h>
#include <cuda_bf16.h>
#include <math.h>

// Problem: inp [B=16, S=4096, D=512] f32, lengths [16] i32
// out [B, S, 513] f32 flat = 33,619,968 floats.
// Strategy: perfectly aligned float4 STORES over the flat output; loads are
// (mostly) unaligned scalar LDGs, dedup'd by L2 sectors. Each thread: 1x STG.128.
//
// total/4 = 8,404,992 float4s = 65664 CTAs x 128 threads exactly.

#define B_DIM 16
#define S_DIM 4096
#define D_DIM 512
#define OD    513
#define PI_F 3.14159265358979323846f

__device__ __forceinline__ float pe_val(unsigned row, const int* __restrict__ lengths) {
    const unsigned b = row >> 12;          // row / 4096
    const unsigned s = row & (S_DIM - 1);
    const int len = __ldg(&lengths[b]);
    float pe = 0.0f;
    if ((int)s < len) {
        float fl = fmaxf((float)len, 1.0f);
        pe = cosf((float)s / fl * PI_F);
    }
    return pe;
}

__global__ __launch_bounds__(128) void concat_pe_flat_kernel(
    const float* __restrict__ inp,
    const int* __restrict__ lengths,
    float* __restrict__ out)
{
    const unsigned idx = blockIdx.x * 128u + threadIdx.x;   // float4 index
    const unsigned f   = idx * 4u;                          // flat float index
    const unsigned row = f / (unsigned)OD;                  // mulhi, cheap
    const unsigned col = f - row * (unsigned)OD;

    float4 v;

    if (col <= (unsigned)(D_DIM - 4)) {
        // Fast path: all 4 elements from one input row, cols col..col+3 < 512.
        const float* src = inp + (size_t)row * D_DIM + col;
        v.x = __ldcs(src + 0);
        v.y = __ldcs(src + 1);
        v.z = __ldcs(src + 2);
        v.w = __ldcs(src + 3);
    } else {
        // Slow path: span includes the pe column and/or next-row head.
        float tmp[4];
        #pragma unroll
        for (int k = 0; k < 4; k++) {
            unsigned ck = col + (unsigned)k;
            if (ck < (unsigned)D_DIM) {
                tmp[k] = __ldcs(inp + (size_t)row * D_DIM + ck);
            } else if (ck == (unsigned)D_DIM) {
                tmp[k] = pe_val(row, lengths);
            } else {
                unsigned r2 = row + 1u;
                unsigned c2 = ck - (unsigned)OD;            // 0..2
                tmp[k] = __ldcs(inp + (size_t)r2 * D_DIM + c2);
            }
        }
        v.x = tmp[0]; v.y = tmp[1]; v.z = tmp[2]; v.w = tmp[3];
    }

    __stcs(reinterpret_cast<float4*>(out) + idx, v);
}

extern "C" void kernel_launch(void* const* d_in, const int* in_sizes, int n_in,
                              void* d_out, int out_size) {
    const float* inp = (const float*)d_in[0];
    const int* lengths = (const int*)d_in[1];
    float* out = (float*)d_out;

    // 16*4096*513 / 4 = 8,404,992 float4s; / 128 threads = 65664 CTAs exactly.
    dim3 grid(65664);
    dim3 block(128);
    concat_pe_flat_kernel<<<grid, block>>>(inp, lengths, out);
}